// round 7
// baseline (speedup 1.0000x reference)
#include <cuda_runtime.h>
#include <cuda_fp16.h>
#include <cstdint>

#define NB 512
#define ND 512
#define NC 200000

static constexpr float cCOS_M  =  0.87758256189037271f;
static constexpr float cSIN_M  =  0.47942553860420301f;
static constexpr float cTHRESH = -0.87758256189037271f;
static constexpr float cMM     =  0.23971276930210150f;
static constexpr float cS      =  64.0f;
static constexpr float cEPS    =  1e-12f;

// Scratch (device globals)
__device__ __align__(1024) __half g_fh[NB * ND];   // normalized feats, fp16 (A operand)
__device__ float g_tl[NB];
__device__ float g_cosm[NB];
__device__ float g_final[NB];
__device__ float g_tnew;

// ---------------------------------------------------------------------------
// helpers
// ---------------------------------------------------------------------------
__device__ __forceinline__ uint32_t smem_u32(const void* p) {
    uint32_t a;
    asm("{ .reg .u64 t; cvta.to.shared.u64 t, %1; cvt.u32.u64 %0, t; }" : "=r"(a) : "l"(p));
    return a;
}
#define CP_ASYNC16(dst, src) \
    asm volatile("cp.async.cg.shared.global [%0], [%1], 16;" :: "r"(dst), "l"(src) : "memory")
#define CP_COMMIT() asm volatile("cp.async.commit_group;" ::: "memory")
#define CP_WAIT2()  asm volatile("cp.async.wait_group 2;" ::: "memory")

__device__ __forceinline__ void mma_f16(float (&c)[4], const uint32_t (&a)[4],
                                        const uint32_t (&b)[2]) {
    asm volatile(
        "mma.sync.aligned.m16n8k16.row.col.f32.f16.f16.f32 "
        "{%0,%1,%2,%3}, {%4,%5,%6,%7}, {%8,%9}, {%0,%1,%2,%3};\n"
        : "+f"(c[0]), "+f"(c[1]), "+f"(c[2]), "+f"(c[3])
        : "r"(a[0]), "r"(a[1]), "r"(a[2]), "r"(a[3]), "r"(b[0]), "r"(b[1]));
}
#define LDMX4(r0, r1, r2, r3, addr)                                           \
    asm volatile("ldmatrix.sync.aligned.m8n8.x4.shared.b16 {%0,%1,%2,%3}, [%4];" \
                 : "=r"(r0), "=r"(r1), "=r"(r2), "=r"(r3) : "r"(addr))
#define LDMX2(r0, r1, addr)                                                   \
    asm volatile("ldmatrix.sync.aligned.m8n8.x2.shared.b16 {%0,%1}, [%2];"    \
                 : "=r"(r0), "=r"(r1) : "r"(addr))
#define STS128(addr, x, y, z, w)                                              \
    asm volatile("st.shared.v4.b32 [%0], {%1,%2,%3,%4};" ::                   \
                 "r"(addr), "r"(x), "r"(y), "r"(z), "r"(w) : "memory")

// ---------------------------------------------------------------------------
// Kernel 1: fused feat-normalize (fp16 A operand) + exact fp32 target logit
// ---------------------------------------------------------------------------
__global__ void k_front(const float* __restrict__ feats, const float* __restrict__ w,
                        const int* __restrict__ labels) {
    int b = blockIdx.x;
    int tid = threadIdx.x;
    const float* x = feats + (size_t)b * ND;
    float f[4];
    float s = 0.f;
#pragma unroll
    for (int j = 0; j < 4; j++) {
        f[j] = x[tid + 128 * j];
        s += f[j] * f[j];
    }
    for (int o = 16; o; o >>= 1) s += __shfl_xor_sync(0xffffffffu, s, o);
    __shared__ float red[8];
    __shared__ float sinv;
    if ((tid & 31) == 0) red[tid >> 5] = s;
    __syncthreads();
    if (tid == 0) sinv = 1.0f / fmaxf(sqrtf(red[0] + red[1] + red[2] + red[3]), cEPS);
    __syncthreads();
    float inv = sinv;
    int lab = labels[b];
    const float* wr = w + (size_t)lab * ND;
    float dot = 0.f, wq = 0.f;
#pragma unroll
    for (int j = 0; j < 4; j++) {
        float fn = f[j] * inv;
        g_fh[(size_t)b * ND + tid + 128 * j] = __float2half_rn(fn);
        float wv = wr[tid + 128 * j];
        dot += fn * wv;
        wq += wv * wv;
    }
    for (int o = 16; o; o >>= 1) {
        dot += __shfl_xor_sync(0xffffffffu, dot, o);
        wq += __shfl_xor_sync(0xffffffffu, wq, o);
    }
    __shared__ float rd[4], rq[4];
    if ((tid & 31) == 0) { rd[tid >> 5] = dot; rq[tid >> 5] = wq; }
    __syncthreads();
    if (tid == 0) {
        float d = rd[0] + rd[1] + rd[2] + rd[3];
        float q = rq[0] + rq[1] + rq[2] + rq[3];
        float tl = d / fmaxf(sqrtf(q), cEPS);
        g_tl[b] = fminf(fmaxf(tl, -1.0f), 1.0f);
    }
}

// ---------------------------------------------------------------------------
// Kernel 2: t_new, cos_theta_m, final
// ---------------------------------------------------------------------------
__global__ void k_scalars(const float* __restrict__ t) {
    int b = threadIdx.x;
    float tl = g_tl[b];
    float s = tl;
    for (int o = 16; o; o >>= 1) s += __shfl_xor_sync(0xffffffffu, s, o);
    __shared__ float red[16];
    if ((b & 31) == 0) red[b >> 5] = s;
    __syncthreads();
    if (b == 0) {
        float tot = 0.f;
#pragma unroll
        for (int i = 0; i < 16; i++) tot += red[i];
        g_tnew = (tot / (float)NB) * 0.01f + 0.99f * t[0];
    }
    float st = sqrtf(fmaxf(1.0f - tl * tl, 0.0f));
    float cm = tl * cCOS_M - st * cSIN_M;
    g_cosm[b] = cm;
    g_final[b] = (tl > cTHRESH) ? cm : (tl - cMM);
}

// ---------------------------------------------------------------------------
// Kernel 3: fused GEMM.
//   cp.async 4-stage ring: A fp16 (direct) + B fp32 (raw weight).
//   Pipelined conversion: during iteration kt, stage kt+1's fp32 B tile is
//   LDS->cvt->STS'd into the idle fp16 buffer while stage kt's MMAs drain.
//   One __syncthreads per kt. Row sumsq accumulated in the cvt phase; epilogue
//   applies 1/||w|| per column then CurricularFace. 2 CTAs/SM.
// ---------------------------------------------------------------------------
#define STAGES 4
#define BK 16
#define KT (ND / BK)   // 32
#define SPAD32 20      // f32 staging row pitch (floats)
#define SPAD_H 24      // f16 row pitch (halfs) -> conflict-free ldmatrix

// dynamic smem layout (bytes)
#define OFF_B32  0
#define SZ_B32   (STAGES * 128 * SPAD32 * 4)          // 40960
#define OFF_A16  (OFF_B32 + SZ_B32)
#define SZ_A16   (STAGES * 128 * SPAD_H * 2)          // 24576
#define OFF_B16  (OFF_A16 + SZ_A16)
#define SZ_B16   (2 * 128 * SPAD_H * 2)               // 12288
#define OFF_SINV (OFF_B16 + SZ_B16)
#define SMEM_TOTAL (OFF_SINV + 128 * 4)               // 78336

__global__ __launch_bounds__(256, 2) void k_gemm(const float* __restrict__ w,
                                                 const int* __restrict__ labels,
                                                 float* __restrict__ out) {
    extern __shared__ __align__(128) char smem[];
    float (*Bs32)[128][SPAD32] = reinterpret_cast<float (*)[128][SPAD32]>(smem + OFF_B32);
    __half (*As16)[128][SPAD_H] = reinterpret_cast<__half (*)[128][SPAD_H]>(smem + OFF_A16);
    __half (*Bs16)[128][SPAD_H] = reinterpret_cast<__half (*)[128][SPAD_H]>(smem + OFF_B16);
    float* sinv = reinterpret_cast<float*>(smem + OFF_SINV);

    const int tid = threadIdx.x;
    const int warp = tid >> 5;
    const int lane = tid & 31;
    const int g = lane >> 2;
    const int tg = lane & 3;
    const int wm = (warp >> 2) * 64;   // 2 warps in m
    const int wn = (warp & 3) * 32;    // 4 warps in n

    const int bm0 = blockIdx.x * 128;  // m tile (fast dim -> weight L2 reuse)
    const int c0 = blockIdx.y * 128;   // class tile

    // staging: row = tid>>1, 8-elem chunk at (tid&1)*8
    const int row = tid >> 1;
    const int off8 = (tid & 1) * 8;
    const int rb = min(c0 + row, NC - 1);
    const __half* srcA = g_fh + (size_t)(bm0 + row) * ND + off8;
    const float* srcB = w + (size_t)rb * ND + off8;

    const int a_row = wm + (lane & 15);
    const int a_col = (lane >> 4) * 8;
    const int b_row = wn + (lane & 7);
    const int b_col = ((lane >> 3) & 1) * 8;

    float acc[4][4][4];
#pragma unroll
    for (int mi = 0; mi < 4; mi++)
#pragma unroll
        for (int ni = 0; ni < 4; ni++)
#pragma unroll
            for (int r = 0; r < 4; r++) acc[mi][ni][r] = 0.f;
    float bq = 0.f;  // partial sum of w^2 (row `row`, 8-col slice per stage)

    // converts fp32 stage `st` (resident in ring) into fp16 buffer st&1 + sumsq
    auto convert_stage = [&](int st) {
        const float4 v0 = *reinterpret_cast<const float4*>(&Bs32[st & 3][row][off8]);
        const float4 v1 = *reinterpret_cast<const float4*>(&Bs32[st & 3][row][off8 + 4]);
        bq += v0.x * v0.x + v0.y * v0.y + v0.z * v0.z + v0.w * v0.w +
              v1.x * v1.x + v1.y * v1.y + v1.z * v1.z + v1.w * v1.w;
        __half2 h0 = __floats2half2_rn(v0.x, v0.y);
        __half2 h1 = __floats2half2_rn(v0.z, v0.w);
        __half2 h2 = __floats2half2_rn(v1.x, v1.y);
        __half2 h3 = __floats2half2_rn(v1.z, v1.w);
        STS128(smem_u32(&Bs16[st & 1][row][off8]),
               *reinterpret_cast<uint32_t*>(&h0), *reinterpret_cast<uint32_t*>(&h1),
               *reinterpret_cast<uint32_t*>(&h2), *reinterpret_cast<uint32_t*>(&h3));
    };

    // prologue: issue stages 0..2
#pragma unroll
    for (int s = 0; s < STAGES - 1; s++) {
        CP_ASYNC16(smem_u32(&As16[s][row][off8]), srcA + s * BK);
        CP_ASYNC16(smem_u32(&Bs32[s][row][off8]), srcB + s * BK);
        CP_ASYNC16(smem_u32(&Bs32[s][row][off8 + 4]), srcB + s * BK + 4);
        CP_COMMIT();
    }
    CP_WAIT2();        // stage 0 resident
    __syncthreads();
    convert_stage(0);  // Bs16[0] ready after next barrier
    __syncthreads();

    for (int kt = 0; kt < KT; kt++) {
        // issue stage kt+3 into ring slot (kt+3)&3
        if (kt + STAGES - 1 < KT) {
            const int ko = (kt + STAGES - 1) * BK;
            const int b = (kt + STAGES - 1) & (STAGES - 1);
            CP_ASYNC16(smem_u32(&As16[b][row][off8]), srcA + ko);
            CP_ASYNC16(smem_u32(&Bs32[b][row][off8]), srcB + ko);
            CP_ASYNC16(smem_u32(&Bs32[b][row][off8 + 4]), srcB + ko + 4);
        }
        CP_COMMIT();
        CP_WAIT2();  // stages <= kt+1 resident (2 newest groups may be pending)

        // MMA on stage kt (A from ring slot kt&3, B from fp16 buffer kt&1)
        const __half (*Asb)[SPAD_H] = As16[kt & 3];
        const __half (*Bsb)[SPAD_H] = Bs16[kt & 1];
        uint32_t af[4][4];
        uint32_t bf[4][2];
#pragma unroll
        for (int mi = 0; mi < 4; mi++) {
            uint32_t addr = smem_u32(&Asb[a_row + mi * 16][a_col]);
            LDMX4(af[mi][0], af[mi][1], af[mi][2], af[mi][3], addr);
        }
#pragma unroll
        for (int ni = 0; ni < 4; ni++) {
            uint32_t addr = smem_u32(&Bsb[b_row + ni * 8][b_col]);
            LDMX2(bf[ni][0], bf[ni][1], addr);
        }
#pragma unroll
        for (int mi = 0; mi < 4; mi++)
#pragma unroll
            for (int ni = 0; ni < 4; ni++) mma_f16(acc[mi][ni], af[mi], bf[ni]);

        // convert stage kt+1 into fp16 buffer (kt+1)&1 while MMAs drain.
        // Safe: buffer (kt+1)&1's readers (iteration kt-1) finished at the
        // previous barrier.
        if (kt + 1 < KT) convert_stage(kt + 1);
        __syncthreads();
    }

    // per-row inverse norms (pair-combine adjacent lanes, stash in smem)
    {
        float q = bq + __shfl_xor_sync(0xffffffffu, bq, 1);
        if ((tid & 1) == 0) sinv[row] = 1.0f / fmaxf(sqrtf(q), cEPS);
    }
    __syncthreads();

    // ---- fused CurricularFace epilogue ----
    const float tnew = g_tnew;
    int ccol[4];
    float2 iw[4];
#pragma unroll
    for (int ni = 0; ni < 4; ni++) {
        int cl = wn + ni * 8 + 2 * tg;
        ccol[ni] = c0 + cl;
        iw[ni].x = sinv[cl];
        iw[ni].y = sinv[cl + 1];
    }

#pragma unroll
    for (int mi = 0; mi < 4; mi++) {
#pragma unroll
        for (int h = 0; h < 2; h++) {
            int m = bm0 + wm + mi * 16 + g + h * 8;
            int lab = labels[m];
            float cm = g_cosm[m];
            float fi = g_final[m];
            float* orow = out + (size_t)m * NC;
#pragma unroll
            for (int ni = 0; ni < 4; ni++) {
                int c = ccol[ni];
                if (c + 1 < NC) {  // NC even: pair fully in-bounds or fully out
                    float x0 = acc[mi][ni][h * 2 + 0] * iw[ni].x;
                    float x1 = acc[mi][ni][h * 2 + 1] * iw[ni].y;
                    x0 = fminf(fmaxf(x0, -1.0f), 1.0f);
                    x1 = fminf(fmaxf(x1, -1.0f), 1.0f);
                    float v0 = (x0 > cm) ? x0 * (tnew + x0) : x0;
                    float v1 = (x1 > cm) ? x1 * (tnew + x1) : x1;
                    if (lab == c) v0 = fi;
                    if (lab == c + 1) v1 = fi;
                    float2 o;
                    o.x = v0 * cS;
                    o.y = v1 * cS;
                    *reinterpret_cast<float2*>(orow + c) = o;
                }
            }
        }
    }
}

// ---------------------------------------------------------------------------
extern "C" void kernel_launch(void* const* d_in, const int* in_sizes, int n_in,
                              void* d_out, int out_size) {
    const float* feats = (const float*)d_in[0];
    const int* labels = (const int*)d_in[1];
    const float* weight = (const float*)d_in[2];
    const float* t = (const float*)d_in[3];
    float* out = (float*)d_out;

    cudaFuncSetAttribute(k_gemm, cudaFuncAttributeMaxDynamicSharedMemorySize, SMEM_TOTAL);

    k_front<<<NB, 128>>>(feats, weight, labels);
    k_scalars<<<1, NB>>>(t);

    dim3 grid(4, (NC + 127) / 128);  // m-tile fast -> 4 CTAs share each weight tile in L2
    k_gemm<<<grid, 256, SMEM_TOTAL>>>(weight, labels, out);
}

// round 8
// speedup vs baseline: 1.3399x; 1.3399x over previous
#include <cuda_runtime.h>
#include <cuda_fp16.h>
#include <cstdint>

#define NB 512
#define ND 512
#define NC 200000
#define NYT 1563            // number of 128-row class tiles
#define WAVE_Y 74           // y-tiles per wave (296 CTAs / 4 x-tiles)

static constexpr float cCOS_M  =  0.87758256189037271f;
static constexpr float cSIN_M  =  0.47942553860420301f;
static constexpr float cTHRESH = -0.87758256189037271f;
static constexpr float cMM     =  0.23971276930210150f;
static constexpr float cS      =  64.0f;
static constexpr float cEPS    =  1e-12f;

// Scratch (device globals)
__device__ __align__(1024) __half g_wh[NC * ND];   // normalized weight, fp16 (filled in-flight)
__device__ __align__(1024) __half g_fh[NB * ND];   // normalized feats, fp16
__device__ float g_tl[NB];
__device__ float g_cosm[NB];
__device__ float g_final[NB];
__device__ float g_tnew;
__device__ int   g_flag[NYT];                      // per-y-tile "weights ready" flags

// ---------------------------------------------------------------------------
// helpers
// ---------------------------------------------------------------------------
__device__ __forceinline__ uint32_t smem_u32(const void* p) {
    uint32_t a;
    asm("{ .reg .u64 t; cvta.to.shared.u64 t, %1; cvt.u32.u64 %0, t; }" : "=r"(a) : "l"(p));
    return a;
}
#define CP_ASYNC16(dst, src) \
    asm volatile("cp.async.cg.shared.global [%0], [%1], 16;" :: "r"(dst), "l"(src) : "memory")
#define CP_COMMIT() asm volatile("cp.async.commit_group;" ::: "memory")
#define CP_WAIT2()  asm volatile("cp.async.wait_group 2;" ::: "memory")
#define CP_WAIT0()  asm volatile("cp.async.wait_group 0;" ::: "memory")

__device__ __forceinline__ void mma_f16(float (&c)[4], const uint32_t (&a)[4],
                                        const uint32_t (&b)[2]) {
    asm volatile(
        "mma.sync.aligned.m16n8k16.row.col.f32.f16.f16.f32 "
        "{%0,%1,%2,%3}, {%4,%5,%6,%7}, {%8,%9}, {%0,%1,%2,%3};\n"
        : "+f"(c[0]), "+f"(c[1]), "+f"(c[2]), "+f"(c[3])
        : "r"(a[0]), "r"(a[1]), "r"(a[2]), "r"(a[3]), "r"(b[0]), "r"(b[1]));
}
#define LDMX4(r0, r1, r2, r3, addr)                                           \
    asm volatile("ldmatrix.sync.aligned.m8n8.x4.shared.b16 {%0,%1,%2,%3}, [%4];" \
                 : "=r"(r0), "=r"(r1), "=r"(r2), "=r"(r3) : "r"(addr))
#define LDMX2(r0, r1, addr)                                                   \
    asm volatile("ldmatrix.sync.aligned.m8n8.x2.shared.b16 {%0,%1}, [%2];"    \
                 : "=r"(r0), "=r"(r1) : "r"(addr))

__device__ __forceinline__ int ld_acquire(const int* p) {
    int v;
    asm volatile("ld.global.acquire.gpu.b32 %0, [%1];" : "=r"(v) : "l"(p) : "memory");
    return v;
}

// ---------------------------------------------------------------------------
// Kernel 1: fused feat-normalize (fp16 A operand) + exact fp32 target logit
// ---------------------------------------------------------------------------
__global__ void k_front(const float* __restrict__ feats, const float* __restrict__ w,
                        const int* __restrict__ labels) {
    int b = blockIdx.x;
    int tid = threadIdx.x;
    const float* x = feats + (size_t)b * ND;
    float f[4];
    float s = 0.f;
#pragma unroll
    for (int j = 0; j < 4; j++) {
        f[j] = x[tid + 128 * j];
        s += f[j] * f[j];
    }
    for (int o = 16; o; o >>= 1) s += __shfl_xor_sync(0xffffffffu, s, o);
    __shared__ float red[4];
    __shared__ float sinv;
    if ((tid & 31) == 0) red[tid >> 5] = s;
    __syncthreads();
    if (tid == 0) sinv = 1.0f / fmaxf(sqrtf(red[0] + red[1] + red[2] + red[3]), cEPS);
    __syncthreads();
    float inv = sinv;
    int lab = labels[b];
    const float* wr = w + (size_t)lab * ND;
    float dot = 0.f, wq = 0.f;
#pragma unroll
    for (int j = 0; j < 4; j++) {
        float fn = f[j] * inv;
        g_fh[(size_t)b * ND + tid + 128 * j] = __float2half_rn(fn);
        float wv = wr[tid + 128 * j];
        dot += fn * wv;
        wq += wv * wv;
    }
    for (int o = 16; o; o >>= 1) {
        dot += __shfl_xor_sync(0xffffffffu, dot, o);
        wq += __shfl_xor_sync(0xffffffffu, wq, o);
    }
    __shared__ float rd[4], rq[4];
    if ((tid & 31) == 0) { rd[tid >> 5] = dot; rq[tid >> 5] = wq; }
    __syncthreads();
    if (tid == 0) {
        float d = rd[0] + rd[1] + rd[2] + rd[3];
        float q = rq[0] + rq[1] + rq[2] + rq[3];
        float tl = d / fmaxf(sqrtf(q), cEPS);
        g_tl[b] = fminf(fmaxf(tl, -1.0f), 1.0f);
    }
}

// ---------------------------------------------------------------------------
// Kernel 2: t_new, cos_theta_m, final  + zero the ready-flags for this launch
// ---------------------------------------------------------------------------
__global__ void k_scalars(const float* __restrict__ t) {
    int b = threadIdx.x;
    for (int i = b; i < NYT; i += 512) g_flag[i] = 0;
    float tl = g_tl[b];
    float s = tl;
    for (int o = 16; o; o >>= 1) s += __shfl_xor_sync(0xffffffffu, s, o);
    __shared__ float red[16];
    if ((b & 31) == 0) red[b >> 5] = s;
    __syncthreads();
    if (b == 0) {
        float tot = 0.f;
#pragma unroll
        for (int i = 0; i < 16; i++) tot += red[i];
        g_tnew = (tot / (float)NB) * 0.01f + 0.99f * t[0];
    }
    float st = sqrtf(fmaxf(1.0f - tl * tl, 0.0f));
    float cm = tl * cCOS_M - st * cSIN_M;
    g_cosm[b] = cm;
    g_final[b] = (tl > cTHRESH) ? cm : (tl - cMM);
}

// ---------------------------------------------------------------------------
// In-GEMM weight tile conversion: normalize 128 rows of y-tile `y` into g_wh.
// 8 warps x 16 rows, warp-per-row reduction, MLP=4 loads. CTA-uniform call.
// ---------------------------------------------------------------------------
__device__ __forceinline__ void convert_y(const float* __restrict__ w, int y) {
    const int tid = threadIdx.x;
    const int warp = tid >> 5;
    const int lane = tid & 31;
    for (int rr = warp; rr < 128; rr += 8) {
        int row = y * 128 + rr;                 // uniform per warp
        if (row >= NC) break;
        const float4* p = reinterpret_cast<const float4*>(w + (size_t)row * ND);
        float4 v[4];
        float s = 0.f;
#pragma unroll
        for (int i = 0; i < 4; i++) {
            v[i] = p[lane + 32 * i];
            s += v[i].x * v[i].x + v[i].y * v[i].y + v[i].z * v[i].z + v[i].w * v[i].w;
        }
        for (int o = 16; o; o >>= 1) s += __shfl_xor_sync(0xffffffffu, s, o);
        float inv = 1.0f / fmaxf(sqrtf(s), cEPS);
        uint2* q = reinterpret_cast<uint2*>(g_wh + (size_t)row * ND);
#pragma unroll
        for (int i = 0; i < 4; i++) {
            __half2 h0 = __floats2half2_rn(v[i].x * inv, v[i].y * inv);
            __half2 h1 = __floats2half2_rn(v[i].z * inv, v[i].w * inv);
            uint2 u;
            u.x = *reinterpret_cast<uint32_t*>(&h0);
            u.y = *reinterpret_cast<uint32_t*>(&h1);
            q[lane + 32 * i] = u;
        }
    }
    __syncthreads();
    if (tid == 0) {
        __threadfence();
        atomicExch(&g_flag[y], 1);
    }
}

// ---------------------------------------------------------------------------
// Kernel 3: R4 GEMM (fp16 m16n8k16, cp.async 4-stage) + in-flight weight prep.
// CTA (x=0, y) converts tile y+74 (and its own tile if y < 74) before compute;
// all CTAs spin on g_flag[y]. Setter's linear id is strictly smaller than any
// waiter's -> safe at any occupancy.
// ---------------------------------------------------------------------------
#define SPAD_H 24      // halfs per smem row (48B) -> conflict-free ldmatrix
#define STAGES 4
#define BK 16
#define KT (ND / BK)   // 32

__global__ __launch_bounds__(256, 2) void k_gemm(const float* __restrict__ w,
                                                 const int* __restrict__ labels,
                                                 float* __restrict__ out) {
    extern __shared__ __align__(128) __half smem[];
    __half (*As)[128][SPAD_H] = reinterpret_cast<__half (*)[128][SPAD_H]>(smem);
    __half (*Bs)[128][SPAD_H] =
        reinterpret_cast<__half (*)[128][SPAD_H]>(smem + STAGES * 128 * SPAD_H);

    const int tid = threadIdx.x;
    const int warp = tid >> 5;
    const int lane = tid & 31;
    const int g = lane >> 2;
    const int tg = lane & 3;
    const int wm = (warp >> 2) * 64;   // 2 warps in m
    const int wn = (warp & 3) * 32;    // 4 warps in n

    const int x = blockIdx.x;
    const int y = blockIdx.y;
    const int bm0 = x * 128;           // m tile (fast dim -> weight L2 reuse)
    const int c0 = y * 128;            // class tile

    // ---- in-flight weight prep (one wave ahead) ----
    if (x == 0) {
        if (y < WAVE_Y) convert_y(w, y);                    // first wave: self
        if (y + WAVE_Y < NYT) convert_y(w, y + WAVE_Y);     // next wave
    }
    // wait for this tile's weights
    if (tid == 0) {
        while (ld_acquire(&g_flag[y]) == 0) __nanosleep(128);
    }
    __syncthreads();

    // ---- R4 GEMM body ----
    const int ra = tid >> 1;
    const int aoff = (tid & 1) * 8;
    const int rb = min(c0 + ra, NC - 1);
    const __half* srcA = g_fh + (size_t)(bm0 + ra) * ND + aoff;
    const __half* srcB = g_wh + (size_t)rb * ND + aoff;

    const int a_row = wm + (lane & 15);
    const int a_col = (lane >> 4) * 8;
    const int b_row = wn + (lane & 7);
    const int b_col = ((lane >> 3) & 1) * 8;

    float acc[4][4][4];
#pragma unroll
    for (int mi = 0; mi < 4; mi++)
#pragma unroll
        for (int ni = 0; ni < 4; ni++)
#pragma unroll
            for (int r = 0; r < 4; r++) acc[mi][ni][r] = 0.f;

    // prologue: stages 0..2
#pragma unroll
    for (int s = 0; s < STAGES - 1; s++) {
        CP_ASYNC16(smem_u32(&As[s][ra][aoff]), srcA + s * BK);
        CP_ASYNC16(smem_u32(&Bs[s][ra][aoff]), srcB + s * BK);
        CP_COMMIT();
    }

    for (int kt = 0; kt < KT; kt++) {
        CP_WAIT2();
        __syncthreads();

        if (kt + STAGES - 1 < KT) {
            int b = (kt + STAGES - 1) & (STAGES - 1);
            CP_ASYNC16(smem_u32(&As[b][ra][aoff]), srcA + (kt + STAGES - 1) * BK);
            CP_ASYNC16(smem_u32(&Bs[b][ra][aoff]), srcB + (kt + STAGES - 1) * BK);
        }
        CP_COMMIT();

        const __half (*Asb)[SPAD_H] = As[kt & (STAGES - 1)];
        const __half (*Bsb)[SPAD_H] = Bs[kt & (STAGES - 1)];

        uint32_t af[4][4];
        uint32_t bf[4][2];
#pragma unroll
        for (int mi = 0; mi < 4; mi++) {
            uint32_t addr = smem_u32(&Asb[a_row + mi * 16][a_col]);
            LDMX4(af[mi][0], af[mi][1], af[mi][2], af[mi][3], addr);
        }
#pragma unroll
        for (int ni = 0; ni < 4; ni++) {
            uint32_t addr = smem_u32(&Bsb[b_row + ni * 8][b_col]);
            LDMX2(bf[ni][0], bf[ni][1], addr);
        }
#pragma unroll
        for (int mi = 0; mi < 4; mi++)
#pragma unroll
            for (int ni = 0; ni < 4; ni++) mma_f16(acc[mi][ni], af[mi], bf[ni]);
    }
    CP_WAIT0();

    // ---- fused CurricularFace epilogue (weights pre-normalized -> acc is cos) ----
    const float tnew = g_tnew;
    int ccol[4];
#pragma unroll
    for (int ni = 0; ni < 4; ni++) ccol[ni] = c0 + wn + ni * 8 + 2 * tg;

#pragma unroll
    for (int mi = 0; mi < 4; mi++) {
#pragma unroll
        for (int h = 0; h < 2; h++) {
            int m = bm0 + wm + mi * 16 + g + h * 8;
            int lab = labels[m];
            float cm = g_cosm[m];
            float fi = g_final[m];
            float* orow = out + (size_t)m * NC;
#pragma unroll
            for (int ni = 0; ni < 4; ni++) {
                int c = ccol[ni];
                if (c + 1 < NC) {  // NC even: pair fully in-bounds or fully out
                    float x0 = fminf(fmaxf(acc[mi][ni][h * 2 + 0], -1.0f), 1.0f);
                    float x1 = fminf(fmaxf(acc[mi][ni][h * 2 + 1], -1.0f), 1.0f);
                    float v0 = (x0 > cm) ? x0 * (tnew + x0) : x0;
                    float v1 = (x1 > cm) ? x1 * (tnew + x1) : x1;
                    if (lab == c) v0 = fi;
                    if (lab == c + 1) v1 = fi;
                    float2 o;
                    o.x = v0 * cS;
                    o.y = v1 * cS;
                    *reinterpret_cast<float2*>(orow + c) = o;
                }
            }
        }
    }
}

// ---------------------------------------------------------------------------
extern "C" void kernel_launch(void* const* d_in, const int* in_sizes, int n_in,
                              void* d_out, int out_size) {
    const float* feats = (const float*)d_in[0];
    const int* labels = (const int*)d_in[1];
    const float* weight = (const float*)d_in[2];
    const float* t = (const float*)d_in[3];
    float* out = (float*)d_out;

    const int smem_bytes = STAGES * 128 * SPAD_H * 2 * (int)sizeof(__half);  // 49152
    cudaFuncSetAttribute(k_gemm, cudaFuncAttributeMaxDynamicSharedMemorySize, smem_bytes);

    k_front<<<NB, 128>>>(feats, weight, labels);
    k_scalars<<<1, NB>>>(t);

    dim3 grid(4, NYT);  // x fast -> linear id = x + 4y; setters precede waiters
    k_gemm<<<grid, 256, smem_bytes>>>(weight, labels, out);
}